// round 13
// baseline (speedup 1.0000x reference)
#include <cuda_runtime.h>
#include <math.h>

#define Nn    1024
#define Hh    4
#define Ff    32
#define CH    128     // H*F
#define DINC  128
#define DE    32
#define EPSB  1e-5f
#define SLOPE 0.2f
#define MAXD  256     // max degree slack (mean ~51, sd ~7)

// ---------------- scratch (no allocs allowed) ----------------
__device__ __align__(16) float g_nproj[Nn * CH];
__device__ __align__(16) float g_skip [Nn * CH];
__device__ float g_ssrc [Nn * Hh];
__device__ float g_stgt [Nn * Hh];
__device__ __align__(16) float g_Y    [Nn * CH];
__device__ __align__(16) float g_mu   [CH];
__device__ __align__(16) float g_rstd [CH];
__device__ __align__(16) float g_Wr   [DE * CH];  // [k][lane*4+q] = W_edge[k][q*32+lane]
__device__ int   g_jlist[Nn * MAXD];
__device__ int   g_ncnt [Nn];
__device__ float g_p1   [32 * CH];
__device__ float g_p2   [32 * CH];
__device__ unsigned g_ctr;
__device__ unsigned g_done;
__device__ volatile int g_flag;

__device__ __forceinline__ float lrelu(float v) { return v > 0.f ? v : SLOPE * v; }

// ---- Blackwell packed f32x2 helpers ----
__device__ __forceinline__ unsigned long long fma2(unsigned long long a,
                                                   unsigned long long b,
                                                   unsigned long long c) {
    unsigned long long d;
    asm("fma.rn.f32x2 %0, %1, %2, %3;" : "=l"(d) : "l"(a), "l"(b), "l"(c));
    return d;
}
__device__ __forceinline__ unsigned long long dup2(float x) {
    unsigned long long r;
    unsigned xi = __float_as_uint(x);
    asm("mov.b64 %0, {%1, %1};" : "=l"(r) : "r"(xi));
    return r;
}
union U64F2 { unsigned long long u; float2 f; };

// ---------------------------------------------------------------------------
// k1: nproj = x@W_proj, skip = x@W_skip, s_src/s_tgt dots, PLUS tail duty:
// deterministic conn compaction for its 8 rows into g_jlist/g_ncnt
// (ordered ballots; warp = (row, 256-j segment), smem prefix across segs).
// Weights-stationary GEMM: W slice in registers, LDS.128 row broadcasts.
// Block 127 also swizzles W_edge -> g_Wr for k2.
// ---------------------------------------------------------------------------
__global__ __launch_bounds__(1024, 1) void k1_proj(
    const float* __restrict__ x,
    const float* __restrict__ conn,
    const float* __restrict__ Wp,
    const float* __restrict__ Wsk,
    const float* __restrict__ a_src,
    const float* __restrict__ a_tgt,
    const float* __restrict__ W_edge)
{
    __shared__ __align__(16) float xs[DINC][8];                 // [k][r]   4 KB
    __shared__ __align__(16) unsigned long long part[4][256][4];// [g][c][pair] 32 KB
    __shared__ float ysm[256][8];                               // combined  8 KB
    __shared__ int   segcnt[8][4];
    const int tid = threadIdx.x;
    const int g   = tid >> 8;         // K-group 0..3
    const int c   = tid & 255;        // m = c>>7, ch = c&127
    const int m   = c >> 7;
    const int ch  = c & 127;
    const int i0  = blockIdx.x * 8;

    // ---- W slice into registers (one-time, fully batched LDGs) ----
    const float* __restrict__ Wm = m ? Wsk : Wp;
    const int kbeg = g * 32;
    float wreg[32];
    #pragma unroll
    for (int kk = 0; kk < 32; kk++)
        wreg[kk] = __ldg(&Wm[(kbeg + kk) * CH + ch]);

    // ---- stage x transposed: xs[k][r] = x[i0+r][k] ----
    {
        const int r = tid >> 7, k = tid & 127;
        xs[k][r] = x[(i0 + r) * DINC + k];
    }
    if (blockIdx.x == 127) {          // one-time W_edge swizzle for k2
        for (int idx = tid; idx < DE * CH; idx += 1024) {
            const int k = idx >> 7, cc = idx & 127;
            g_Wr[k * CH + (cc & 31) * 4 + (cc >> 5)] = W_edge[idx];
        }
    }
    __syncthreads();

    // ---- main loop: LDS.128 (two row-pairs each) + packed FMA ----
    const ulonglong2* __restrict__ xs4 =
        reinterpret_cast<const ulonglong2*>(xs);   // xs4[k*2+h] = pairs {2h,2h+1}
    unsigned long long acc0 = 0ull, acc1 = 0ull, acc2 = 0ull, acc3 = 0ull;
    #pragma unroll
    for (int kk = 0; kk < 32; kk++) {
        const unsigned long long wv = dup2(wreg[kk]);
        const int kb = (kbeg + kk) * 2;
        const ulonglong2 p01 = xs4[kb + 0];
        const ulonglong2 p23 = xs4[kb + 1];
        acc0 = fma2(p01.x, wv, acc0);
        acc1 = fma2(p01.y, wv, acc1);
        acc2 = fma2(p23.x, wv, acc2);
        acc3 = fma2(p23.y, wv, acc3);
    }
    part[g][c][0] = acc0;
    part[g][c][1] = acc1;
    part[g][c][2] = acc2;
    part[g][c][3] = acc3;
    __syncthreads();

    // ---- combine 4 K-groups; write outputs; keep in ysm for dots ----
    {
        const int c2 = tid & 255;
        const int rr = tid >> 8;            // 0..3 -> rows rr and rr+4
        const int m2 = c2 >> 7, ch2 = c2 & 127;
        float* __restrict__ dst = m2 ? g_skip : g_nproj;
        #pragma unroll
        for (int hh = 0; hh < 2; hh++) {
            const int r = rr + hh * 4;
            const int p = r >> 1, sel = r & 1;
            U64F2 u0, u1, u2, u3;
            u0.u = part[0][c2][p]; u1.u = part[1][c2][p];
            u2.u = part[2][c2][p]; u3.u = part[3][c2][p];
            const float a = (sel ? u0.f.y : u0.f.x) + (sel ? u1.f.y : u1.f.x)
                          + (sel ? u2.f.y : u2.f.x) + (sel ? u3.f.y : u3.f.x);
            dst[(i0 + r) * CH + ch2] = a;
            ysm[c2][r] = a;
        }
    }
    __syncthreads();

    const int w    = tid >> 5;
    const int lane = tid & 31;

    // ---- head dots: warp w -> (row = w>>2, head = w&3) ----
    {
        const int row = w >> 2;
        const int hd  = w & 3;
        const int chn = hd * 32 + lane;
        const float yv = ysm[chn][row];
        float s1 = yv * __ldg(&a_src[chn]);
        float s2 = yv * __ldg(&a_tgt[chn]);
        #pragma unroll
        for (int o = 16; o > 0; o >>= 1) {
            s1 += __shfl_xor_sync(0xffffffffu, s1, o);
            s2 += __shfl_xor_sync(0xffffffffu, s2, o);
        }
        if (lane == 0) {
            g_ssrc[(i0 + row) * Hh + hd] = s1;
            g_stgt[(i0 + row) * Hh + hd] = s2;
        }
    }

    // ---- tail duty: deterministic conn compaction for rows i0..i0+7 ----
    // warp = (r = w>>2, seg = w&3); seg covers j in [seg*256, seg*256+256)
    {
        const int r   = w >> 2;
        const int seg = w & 3;
        const float* __restrict__ crow = &conn[(long)(i0 + r) * Nn + seg * 256];
        float cv[8];
        #pragma unroll
        for (int t = 0; t < 8; t++) cv[t] = __ldg(&crow[t * 32 + lane]);
        int  pos[8];
        unsigned onmask = 0u;
        int cnt = 0;
        #pragma unroll
        for (int t = 0; t < 8; t++) {
            const bool on = cv[t] > -1e8f;
            if (on) onmask |= (1u << t);
            const unsigned bal = __ballot_sync(0xffffffffu, on);
            pos[t] = cnt + __popc(bal & ((1u << lane) - 1u));
            cnt += __popc(bal);
        }
        if (lane == 0) segcnt[r][seg] = cnt;
        __syncthreads();
        int off = 0, tot = 0;
        #pragma unroll
        for (int s = 0; s < 4; s++) {
            const int sc = segcnt[r][s];
            if (s < seg) off += sc;
            tot += sc;
        }
        if (seg == 0 && lane == 0) g_ncnt[i0 + r] = tot;
        int* __restrict__ jrow = &g_jlist[(i0 + r) * MAXD + off];
        #pragma unroll
        for (int t = 0; t < 8; t++)
            if (onmask & (1u << t)) jrow[pos[t]] = seg * 256 + t * 32 + lane;
    }
}

// ---------------------------------------------------------------------------
// k2: per-row sparse attention, one block per row i. NO PROLOGUE: edge list
// comes precompacted from k1 (g_jlist/g_ncnt), so warps start the matvec
// immediately. -1e9 edges have bit-exact-zero softmax weight in fp32,
// matching the reference. 8 warps x 8-edge batches; packed f32x2 matvec;
// no-max softmax (scores O(1)); reduce-and-distribute + coalesced gather.
// ---------------------------------------------------------------------------
__global__ __launch_bounds__(256) void k2_attn(
    const float* __restrict__ e,
    const float* __restrict__ b_edge,
    const float* __restrict__ a_edge)
{
    __shared__ __align__(16) float es[8][DE * 10];   // [warp][k*10+b]
    __shared__ float4 acc_sm[8][32];
    __shared__ float  l_sm[8][Hh];

    const int tid  = threadIdx.x;
    const int lane = tid & 31;
    const int w    = tid >> 5;
    const int i    = blockIdx.x;

    const int nact = __ldg(&g_ncnt[i]);
    const int* __restrict__ jl = &g_jlist[i * MAXD];

    const float4* __restrict__ Wr4 = reinterpret_cast<const float4*>(g_Wr);
    const float4 bev = make_float4(b_edge[lane], b_edge[32 + lane],
                                   b_edge[64 + lane], b_edge[96 + lane]);
    const float4 aev = make_float4(a_edge[lane], a_edge[32 + lane],
                                   a_edge[64 + lane], a_edge[96 + lane]);
    const int   head  = lane >> 3;
    const float src_h = __ldg(&g_ssrc[i * Hh + head]);
    const bool  hi16  = (lane & 16) != 0;
    const bool  hi8   = (lane & 8)  != 0;

    float4 oacc = make_float4(0.f, 0.f, 0.f, 0.f);
    float  lacc = 0.f;
    float* esw  = es[w];

    for (int base = w * 8; base < nact; base += 64) {
        int  jj[8];
        bool act[8];
        #pragma unroll
        for (int b = 0; b < 8; b++) {
            const int idx = base + b;
            act[b] = idx < nact;
            jj[b]  = __ldg(&jl[act[b] ? idx : (nact - 1)]);
        }

        __syncwarp();
        #pragma unroll
        for (int b = 0; b < 8; b++)
            esw[lane * 10 + b] = __ldg(&e[((long)i * Nn + jj[b]) * DE + lane]);
        __syncwarp();

        unsigned long long acc2[4][4];
        #pragma unroll
        for (int q = 0; q < 4; q++)
            #pragma unroll
            for (int t = 0; t < 4; t++) acc2[q][t] = 0ull;

        #pragma unroll 8
        for (int k = 0; k < DE; k++) {
            const float4 wv = __ldg(&Wr4[k * 32 + lane]);
            const unsigned long long wx = dup2(wv.x), wy = dup2(wv.y),
                                     wz = dup2(wv.z), ww2 = dup2(wv.w);
            #pragma unroll
            for (int t = 0; t < 4; t++) {
                const unsigned long long ee =
                    *reinterpret_cast<const unsigned long long*>(&esw[k * 10 + 2 * t]);
                acc2[0][t] = fma2(ee, wx,  acc2[0][t]);
                acc2[1][t] = fma2(ee, wy,  acc2[1][t]);
                acc2[2][t] = fma2(ee, wz,  acc2[2][t]);
                acc2[3][t] = fma2(ee, ww2, acc2[3][t]);
            }
        }

        #pragma unroll
        for (int b = 0; b < 8; b++) {
            const int t = b >> 1;
            U64F2 c0, c1, c2, c3;
            c0.u = acc2[0][t]; c1.u = acc2[1][t]; c2.u = acc2[2][t]; c3.u = acc2[3][t];
            const float s0 = (b & 1) ? c0.f.y : c0.f.x;
            const float s1 = (b & 1) ? c1.f.y : c1.f.x;
            const float s2 = (b & 1) ? c2.f.y : c2.f.x;
            const float s3 = (b & 1) ? c3.f.y : c3.f.x;

            const float a0 = lrelu(s0 + bev.x) * aev.x;
            const float a1 = lrelu(s1 + bev.y) * aev.y;
            const float a2 = lrelu(s2 + bev.z) * aev.z;
            const float a3 = lrelu(s3 + bev.w) * aev.w;

            float x0 = hi16 ? a2 : a0;
            float x1 = hi16 ? a3 : a1;
            const float y0 = hi16 ? a0 : a2;
            const float y1 = hi16 ? a1 : a3;
            x0 += __shfl_xor_sync(0xffffffffu, y0, 16);
            x1 += __shfl_xor_sync(0xffffffffu, y1, 16);
            float r = (hi8 ? x1 : x0) + __shfl_xor_sync(0xffffffffu, hi8 ? x0 : x1, 8);
            r += __shfl_xor_sync(0xffffffffu, r, 4);
            r += __shfl_xor_sync(0xffffffffu, r, 2);
            r += __shfl_xor_sync(0xffffffffu, r, 1);

            const float stg = __ldg(&g_stgt[jj[b] * Hh + head]);
            const float sc  = lrelu(src_h + stg + r);
            const float p   = act[b] ? __expf(sc) : 0.f;
            lacc += p;
            const float4 nv =
                __ldg(reinterpret_cast<const float4*>(&g_nproj[(long)jj[b] * CH + lane * 4]));
            oacc.x = fmaf(p, nv.x, oacc.x);
            oacc.y = fmaf(p, nv.y, oacc.y);
            oacc.z = fmaf(p, nv.z, oacc.z);
            oacc.w = fmaf(p, nv.w, oacc.w);
        }
    }

    acc_sm[w][lane] = oacc;
    if ((lane & 7) == 0) l_sm[w][head] = lacc;
    __syncthreads();

    if (tid < 32) {
        float4 V = make_float4(0.f, 0.f, 0.f, 0.f);
        float  L = 0.f;
        const int hq = lane >> 3;
        #pragma unroll
        for (int ww = 0; ww < 8; ww++) {
            const float4 a = acc_sm[ww][lane];
            V.x += a.x; V.y += a.y; V.z += a.z; V.w += a.w;
            L   += l_sm[ww][hq];
        }
        const float invL = 1.f / L;
        const float4 sk = *reinterpret_cast<const float4*>(&g_skip[i * CH + lane * 4]);
        float4 yv;
        yv.x = fmaf(V.x, invL, sk.x);
        yv.y = fmaf(V.y, invL, sk.y);
        yv.z = fmaf(V.z, invL, sk.z);
        yv.w = fmaf(V.w, invL, sk.w);
        *reinterpret_cast<float4*>(&g_Y[i * CH + lane * 4]) = yv;
    }
}

// ---------------------------------------------------------------------------
// k34: fused batch-stats + BN apply + ELU. 32 resident blocks, flag spin.
// ---------------------------------------------------------------------------
__global__ __launch_bounds__(256) void k34_bn(
    const float* __restrict__ gamma,
    const float* __restrict__ beta,
    const float* __restrict__ bias,
    float* __restrict__ out)
{
    const int b    = blockIdx.x;
    const int tid  = threadIdx.x;
    const int c    = tid & 127;
    const int half = tid >> 7;

    float s = 0.f, s2 = 0.f;
    const int r0 = b * 32 + half * 16;
    #pragma unroll 4
    for (int r = 0; r < 16; r++) {
        const float v = g_Y[(r0 + r) * CH + c];
        s += v;
        s2 = fmaf(v, v, s2);
    }

    __shared__ float sh1[CH], sh2[CH];
    __shared__ int   amlast;
    if (half == 1) { sh1[c] = s; sh2[c] = s2; }
    __syncthreads();
    if (half == 0) {
        g_p1[b * CH + c] = s  + sh1[c];
        g_p2[b * CH + c] = s2 + sh2[c];
    }
    __threadfence();
    __syncthreads();
    if (tid == 0) amlast = (atomicAdd(&g_ctr, 1u) == 31u);
    __syncthreads();

    if (amlast) {
        if (tid < CH) {
            float S = 0.f, S2 = 0.f;
            #pragma unroll
            for (int bb = 0; bb < 32; bb++) {
                S  += g_p1[bb * CH + tid];
                S2 += g_p2[bb * CH + tid];
            }
            const float mu  = S  * (1.f / Nn);
            const float var = S2 * (1.f / Nn) - mu * mu;
            g_mu[tid]   = mu;
            g_rstd[tid] = rsqrtf(var + EPSB);
        }
        __threadfence();
        __syncthreads();
        if (tid == 0) g_flag = 1;
    }

    if (tid == 0) { while (g_flag == 0) __nanosleep(64); }
    __syncthreads();
    __threadfence();

    #pragma unroll
    for (int rr = 0; rr < 4; rr++) {
        const int idx4 = b * 1024 + rr * 256 + tid;
        const int c4   = idx4 & 31;
        const float4 v  = reinterpret_cast<const float4*>(g_Y)[idx4];
        const float4 mu = reinterpret_cast<const float4*>(g_mu)[c4];
        const float4 rs = reinterpret_cast<const float4*>(g_rstd)[c4];
        const float4 ga = reinterpret_cast<const float4*>(gamma)[c4];
        const float4 be = reinterpret_cast<const float4*>(beta)[c4];
        const float4 bi = reinterpret_cast<const float4*>(bias)[c4];
        float4 r; float o;
        o = fmaf((v.x - mu.x) * rs.x, ga.x, be.x) + bi.x;  r.x = o > 0.f ? o : expm1f(o);
        o = fmaf((v.y - mu.y) * rs.y, ga.y, be.y) + bi.y;  r.y = o > 0.f ? o : expm1f(o);
        o = fmaf((v.z - mu.z) * rs.z, ga.z, be.z) + bi.z;  r.z = o > 0.f ? o : expm1f(o);
        o = fmaf((v.w - mu.w) * rs.w, ga.w, be.w) + bi.w;  r.w = o > 0.f ? o : expm1f(o);
        reinterpret_cast<float4*>(out)[idx4] = r;
    }

    __syncthreads();
    if (tid == 0) {
        if (atomicAdd(&g_done, 1u) == 31u) {
            g_ctr  = 0u;
            g_done = 0u;
            g_flag = 0;
        }
    }
}

// ---------------------------------------------------------------------------
extern "C" void kernel_launch(void* const* d_in, const int* in_sizes, int n_in,
                              void* d_out, int out_size)
{
    const float* x     = (const float*)d_in[0];
    const float* e     = (const float*)d_in[1];
    const float* conn  = (const float*)d_in[2];
    const float* Wp    = (const float*)d_in[3];
    const float* We    = (const float*)d_in[4];
    const float* be    = (const float*)d_in[5];
    const float* asrc  = (const float*)d_in[6];
    const float* atgt  = (const float*)d_in[7];
    const float* aedg  = (const float*)d_in[8];
    const float* Wsk   = (const float*)d_in[9];
    const float* gamma = (const float*)d_in[10];
    const float* beta  = (const float*)d_in[11];
    const float* bias  = (const float*)d_in[12];
    float* out = (float*)d_out;

    k1_proj<<<Nn / 8, 1024>>>(x, conn, Wp, Wsk, asrc, atgt, We);
    k2_attn<<<Nn, 256>>>(e, be, aedg);
    k34_bn<<<32, 256>>>(gamma, beta, bias, out);
}

// round 15
// speedup vs baseline: 1.0817x; 1.0817x over previous
#include <cuda_runtime.h>
#include <math.h>

#define Nn    1024
#define Hh    4
#define Ff    32
#define CH    128     // H*F
#define DINC  128
#define DE    32
#define EPSB  1e-5f
#define SLOPE 0.2f

// ---------------- scratch (no allocs allowed) ----------------
__device__ __align__(16) float g_nproj[Nn * CH];
__device__ __align__(16) float g_skip [Nn * CH];
__device__ float g_ssrc [Nn * Hh];
__device__ float g_stgt [Nn * Hh];
__device__ __align__(16) float g_mu   [CH];
__device__ __align__(16) float g_rstd [CH];
__device__ __align__(16) float g_Wr   [DE * CH];  // [k][lane*4+q] = W_edge[k][q*32+lane]
__device__ float g_p1   [128 * CH];
__device__ float g_p2   [128 * CH];
__device__ unsigned g_ctr;
__device__ unsigned g_done;
__device__ volatile int g_flag;

__device__ __forceinline__ float lrelu(float v) { return v > 0.f ? v : SLOPE * v; }

// ---- Blackwell packed f32x2 helpers ----
__device__ __forceinline__ unsigned long long fma2(unsigned long long a,
                                                   unsigned long long b,
                                                   unsigned long long c) {
    unsigned long long d;
    asm("fma.rn.f32x2 %0, %1, %2, %3;" : "=l"(d) : "l"(a), "l"(b), "l"(c));
    return d;
}
__device__ __forceinline__ unsigned long long dup2(float x) {
    unsigned long long r;
    unsigned xi = __float_as_uint(x);
    asm("mov.b64 %0, {%1, %1};" : "=l"(r) : "r"(xi));
    return r;
}
union U64F2 { unsigned long long u; float2 f; };

// ---------------------------------------------------------------------------
// k1 (round-11 form, measured 10.5us): nproj = x@W_proj, skip = x@W_skip,
// s_src/s_tgt dots. Weights-stationary: W slice in registers, LDS row
// broadcasts, K-split x4 combined in smem. Block 127 swizzles W_edge->g_Wr.
// ---------------------------------------------------------------------------
__global__ __launch_bounds__(1024, 1) void k1_proj(
    const float* __restrict__ x,
    const float* __restrict__ Wp,
    const float* __restrict__ Wsk,
    const float* __restrict__ a_src,
    const float* __restrict__ a_tgt,
    const float* __restrict__ W_edge)
{
    __shared__ __align__(16) float xs[DINC][8];                 // [k][r]   4 KB
    __shared__ __align__(16) unsigned long long part[4][256][4];// 32 KB
    __shared__ float ysm[256][8];                               //  8 KB
    const int tid = threadIdx.x;
    const int g   = tid >> 8;
    const int c   = tid & 255;
    const int m   = c >> 7;
    const int ch  = c & 127;
    const int i0  = blockIdx.x * 8;

    const float* __restrict__ Wm = m ? Wsk : Wp;
    const int kbeg = g * 32;
    float wreg[32];
    #pragma unroll
    for (int kk = 0; kk < 32; kk++)
        wreg[kk] = __ldg(&Wm[(kbeg + kk) * CH + ch]);

    {
        const int r = tid >> 7, k = tid & 127;
        xs[k][r] = x[(i0 + r) * DINC + k];
    }
    if (blockIdx.x == 127) {
        for (int idx = tid; idx < DE * CH; idx += 1024) {
            const int k = idx >> 7, cc = idx & 127;
            g_Wr[k * CH + (cc & 31) * 4 + (cc >> 5)] = W_edge[idx];
        }
    }
    __syncthreads();

    const ulonglong2* __restrict__ xs4 =
        reinterpret_cast<const ulonglong2*>(xs);
    unsigned long long acc0 = 0ull, acc1 = 0ull, acc2 = 0ull, acc3 = 0ull;
    #pragma unroll
    for (int kk = 0; kk < 32; kk++) {
        const unsigned long long wv = dup2(wreg[kk]);
        const int kb = (kbeg + kk) * 2;
        const ulonglong2 p01 = xs4[kb + 0];
        const ulonglong2 p23 = xs4[kb + 1];
        acc0 = fma2(p01.x, wv, acc0);
        acc1 = fma2(p01.y, wv, acc1);
        acc2 = fma2(p23.x, wv, acc2);
        acc3 = fma2(p23.y, wv, acc3);
    }
    part[g][c][0] = acc0;
    part[g][c][1] = acc1;
    part[g][c][2] = acc2;
    part[g][c][3] = acc3;
    __syncthreads();

    {
        const int c2 = tid & 255;
        const int rr = tid >> 8;
        const int m2 = c2 >> 7, ch2 = c2 & 127;
        float* __restrict__ dst = m2 ? g_skip : g_nproj;
        #pragma unroll
        for (int hh = 0; hh < 2; hh++) {
            const int r = rr + hh * 4;
            const int p = r >> 1, sel = r & 1;
            U64F2 u0, u1, u2, u3;
            u0.u = part[0][c2][p]; u1.u = part[1][c2][p];
            u2.u = part[2][c2][p]; u3.u = part[3][c2][p];
            const float a = (sel ? u0.f.y : u0.f.x) + (sel ? u1.f.y : u1.f.x)
                          + (sel ? u2.f.y : u2.f.x) + (sel ? u3.f.y : u3.f.x);
            dst[(i0 + r) * CH + ch2] = a;
            ysm[c2][r] = a;
        }
    }
    __syncthreads();

    {
        const int w    = tid >> 5;
        const int lane = tid & 31;
        const int row  = w >> 2;
        const int hd   = w & 3;
        const int chn  = hd * 32 + lane;
        const float yv = ysm[chn][row];
        float s1 = yv * __ldg(&a_src[chn]);
        float s2 = yv * __ldg(&a_tgt[chn]);
        #pragma unroll
        for (int o = 16; o > 0; o >>= 1) {
            s1 += __shfl_xor_sync(0xffffffffu, s1, o);
            s2 += __shfl_xor_sync(0xffffffffu, s2, o);
        }
        if (lane == 0) {
            g_ssrc[(i0 + row) * Hh + hd] = s1;
            g_stgt[(i0 + row) * Hh + hd] = s2;
        }
    }
}

// ---------------------------------------------------------------------------
// k2_fused: sparse attention (warp-per-row, pipelined) + fused BatchNorm+ELU.
// Grid 128 x 256 (one wave, all blocks resident -> flag-spin is safe).
// Per warp: compact its row's edges (ordered ballots, deterministic),
// then double-buffered batches of 8 edges: prefetch e for batch t+1 while
// computing batch t (packed f32x2 matvec + no-max softmax, O(1) scores;
// -1e9 edges are bit-exact zero-weight in fp32, matching reference).
// Row results stay in smem; block partial sums -> ticket -> last block
// computes mu/rstd (fixed-order loops) -> flag -> all apply BN+bias+ELU.
// Counters reset each launch (graph-replay safe).
// ---------------------------------------------------------------------------
__global__ __launch_bounds__(256, 1) void k2_fused(
    const float* __restrict__ e,
    const float* __restrict__ conn,
    const float* __restrict__ b_edge,
    const float* __restrict__ a_edge,
    const float* __restrict__ gamma,
    const float* __restrict__ beta,
    const float* __restrict__ bias,
    float* __restrict__ out)
{
    __shared__ __align__(16) float es[8][2][DE * 10];  // 20 KB double buffer
    __shared__ int   jsm[8][128];                      //  4 KB compacted lists
    __shared__ __align__(16) float ysm[8][CH];         //  4 KB row results
    __shared__ int   amlast;

    const int tid  = threadIdx.x;
    const int lane = tid & 31;
    const int w    = tid >> 5;
    const int blk  = blockIdx.x;
    const int i    = blk * 8 + w;     // this warp's row

    // ---- warp-local deterministic compaction of row i ----
    int nact = 0;
    {
        const float4* __restrict__ crow =
            reinterpret_cast<const float4*>(&conn[(long)i * Nn]);
        #pragma unroll
        for (int t2 = 0; t2 < 8; t2++) {
            const float4 cv = __ldg(&crow[t2 * 32 + lane]);
            #pragma unroll
            for (int q = 0; q < 4; q++) {
                const float v = q == 0 ? cv.x : q == 1 ? cv.y : q == 2 ? cv.z : cv.w;
                const bool on = v > -1e8f;
                const unsigned bal = __ballot_sync(0xffffffffu, on);
                if (on)
                    jsm[w][nact + __popc(bal & ((1u << lane) - 1u))] =
                        t2 * 128 + lane * 4 + q;
                nact += __popc(bal);
            }
        }
    }
    __syncwarp();

    const float4* __restrict__ Wr4 = reinterpret_cast<const float4*>(g_Wr);
    const float4 bev = make_float4(b_edge[lane], b_edge[32 + lane],
                                   b_edge[64 + lane], b_edge[96 + lane]);
    const float4 aev = make_float4(a_edge[lane], a_edge[32 + lane],
                                   a_edge[64 + lane], a_edge[96 + lane]);
    const int   head  = lane >> 3;
    const float src_h = __ldg(&g_ssrc[i * Hh + head]);
    const bool  hi16  = (lane & 16) != 0;
    const bool  hi8   = (lane & 8)  != 0;

    float4 oacc = make_float4(0.f, 0.f, 0.f, 0.f);
    float  lacc = 0.f;

    const int nb = (nact + 7) >> 3;
    float ev[8];
    // prefetch batch 0
    #pragma unroll
    for (int b = 0; b < 8; b++) {
        const int idx = b < nact ? b : (nact - 1);
        const int jb  = jsm[w][idx];
        ev[b] = __ldg(&e[((long)i * Nn + jb) * DE + lane]);
    }

    for (int t = 0; t < nb; t++) {
        float* esw = &es[w][t & 1][0];
        #pragma unroll
        for (int b = 0; b < 8; b++) esw[lane * 10 + b] = ev[b];
        __syncwarp();

        if (t + 1 < nb) {           // prefetch next batch while computing
            #pragma unroll
            for (int b = 0; b < 8; b++) {
                int idx = (t + 1) * 8 + b;
                idx = idx < nact ? idx : (nact - 1);
                const int jb = jsm[w][idx];
                ev[b] = __ldg(&e[((long)i * Nn + jb) * DE + lane]);
            }
        }

        unsigned long long acc2[4][4];
        #pragma unroll
        for (int q = 0; q < 4; q++)
            #pragma unroll
            for (int t2 = 0; t2 < 4; t2++) acc2[q][t2] = 0ull;

        #pragma unroll 8
        for (int k = 0; k < DE; k++) {
            const float4 wv = __ldg(&Wr4[k * 32 + lane]);
            const unsigned long long wx = dup2(wv.x), wy = dup2(wv.y),
                                     wz = dup2(wv.z), ww2 = dup2(wv.w);
            #pragma unroll
            for (int t2 = 0; t2 < 4; t2++) {
                const unsigned long long ee =
                    *reinterpret_cast<const unsigned long long*>(&esw[k * 10 + 2 * t2]);
                acc2[0][t2] = fma2(ee, wx,  acc2[0][t2]);
                acc2[1][t2] = fma2(ee, wy,  acc2[1][t2]);
                acc2[2][t2] = fma2(ee, wz,  acc2[2][t2]);
                acc2[3][t2] = fma2(ee, ww2, acc2[3][t2]);
            }
        }

        #pragma unroll
        for (int b = 0; b < 8; b++) {
            const int idx  = t * 8 + b;
            const bool act = idx < nact;
            const int  jb  = jsm[w][act ? idx : (nact - 1)];
            const int  tp  = b >> 1;
            U64F2 c0, c1, c2, c3;
            c0.u = acc2[0][tp]; c1.u = acc2[1][tp];
            c2.u = acc2[2][tp]; c3.u = acc2[3][tp];
            const float s0 = (b & 1) ? c0.f.y : c0.f.x;
            const float s1 = (b & 1) ? c1.f.y : c1.f.x;
            const float s2 = (b & 1) ? c2.f.y : c2.f.x;
            const float s3 = (b & 1) ? c3.f.y : c3.f.x;

            const float a0 = lrelu(s0 + bev.x) * aev.x;
            const float a1 = lrelu(s1 + bev.y) * aev.y;
            const float a2 = lrelu(s2 + bev.z) * aev.z;
            const float a3 = lrelu(s3 + bev.w) * aev.w;

            float x0 = hi16 ? a2 : a0;
            float x1 = hi16 ? a3 : a1;
            const float y0 = hi16 ? a0 : a2;
            const float y1 = hi16 ? a1 : a3;
            x0 += __shfl_xor_sync(0xffffffffu, y0, 16);
            x1 += __shfl_xor_sync(0xffffffffu, y1, 16);
            float r = (hi8 ? x1 : x0) + __shfl_xor_sync(0xffffffffu, hi8 ? x0 : x1, 8);
            r += __shfl_xor_sync(0xffffffffu, r, 4);
            r += __shfl_xor_sync(0xffffffffu, r, 2);
            r += __shfl_xor_sync(0xffffffffu, r, 1);

            const float stg = __ldg(&g_stgt[jb * Hh + head]);
            const float sc  = lrelu(src_h + stg + r);
            const float p   = act ? __expf(sc) : 0.f;
            lacc += p;
            const float4 nv =
                __ldg(reinterpret_cast<const float4*>(&g_nproj[(long)jb * CH + lane * 4]));
            oacc.x = fmaf(p, nv.x, oacc.x);
            oacc.y = fmaf(p, nv.y, oacc.y);
            oacc.z = fmaf(p, nv.z, oacc.z);
            oacc.w = fmaf(p, nv.w, oacc.w);
        }
        __syncwarp();
    }

    // ---- finish row: V/L + skip, stash in smem ----
    {
        const float invL = 1.f / lacc;
        const float4 sk  =
            __ldg(reinterpret_cast<const float4*>(&g_skip[(long)i * CH + lane * 4]));
        float4 yv;
        yv.x = fmaf(oacc.x, invL, sk.x);
        yv.y = fmaf(oacc.y, invL, sk.y);
        yv.z = fmaf(oacc.z, invL, sk.z);
        yv.w = fmaf(oacc.w, invL, sk.w);
        *reinterpret_cast<float4*>(&ysm[w][lane * 4]) = yv;
    }
    __syncthreads();

    // ---- block partial sums per channel (fixed order) ----
    if (tid < CH) {
        float s = 0.f, s2 = 0.f;
        #pragma unroll
        for (int r = 0; r < 8; r++) {
            const float v = ysm[r][tid];
            s += v;
            s2 = fmaf(v, v, s2);
        }
        g_p1[blk * CH + tid] = s;
        g_p2[blk * CH + tid] = s2;
    }
    __threadfence();
    __syncthreads();
    if (tid == 0) amlast = (atomicAdd(&g_ctr, 1u) == 127u);
    __syncthreads();

    if (amlast) {
        if (tid < CH) {
            float S = 0.f, S2 = 0.f;
            #pragma unroll 8
            for (int bb = 0; bb < 128; bb++) {
                S  += g_p1[bb * CH + tid];
                S2 += g_p2[bb * CH + tid];
            }
            const float mu  = S  * (1.f / Nn);
            const float var = S2 * (1.f / Nn) - mu * mu;
            g_mu[tid]   = mu;
            g_rstd[tid] = rsqrtf(var + EPSB);
        }
        __threadfence();
        __syncthreads();
        if (tid == 0) g_flag = 1;
    }

    if (tid == 0) { while (g_flag == 0) __nanosleep(64); }
    __syncthreads();
    __threadfence();

    // ---- apply BN + bias + ELU to own row, straight from smem ----
    {
        const float4 v  = *reinterpret_cast<const float4*>(&ysm[w][lane * 4]);
        const float4 mu = __ldg(&reinterpret_cast<const float4*>(g_mu)[lane]);
        const float4 rs = __ldg(&reinterpret_cast<const float4*>(g_rstd)[lane]);
        const float4 ga = __ldg(&reinterpret_cast<const float4*>(gamma)[lane]);
        const float4 be = __ldg(&reinterpret_cast<const float4*>(beta)[lane]);
        const float4 bi = __ldg(&reinterpret_cast<const float4*>(bias)[lane]);
        float4 r; float o;
        o = fmaf((v.x - mu.x) * rs.x, ga.x, be.x) + bi.x;  r.x = o > 0.f ? o : expm1f(o);
        o = fmaf((v.y - mu.y) * rs.y, ga.y, be.y) + bi.y;  r.y = o > 0.f ? o : expm1f(o);
        o = fmaf((v.z - mu.z) * rs.z, ga.z, be.z) + bi.z;  r.z = o > 0.f ? o : expm1f(o);
        o = fmaf((v.w - mu.w) * rs.w, ga.w, be.w) + bi.w;  r.w = o > 0.f ? o : expm1f(o);
        reinterpret_cast<float4*>(&out[(long)i * CH])[lane] = r;
    }

    // ---- cleanup for next graph replay ----
    __syncthreads();
    if (tid == 0) {
        if (atomicAdd(&g_done, 1u) == 127u) {
            g_ctr  = 0u;
            g_done = 0u;
            g_flag = 0;
        }
    }
}

// ---------------------------------------------------------------------------
extern "C" void kernel_launch(void* const* d_in, const int* in_sizes, int n_in,
                              void* d_out, int out_size)
{
    const float* x     = (const float*)d_in[0];
    const float* e     = (const float*)d_in[1];
    const float* conn  = (const float*)d_in[2];
    const float* Wp    = (const float*)d_in[3];
    const float* We    = (const float*)d_in[4];
    const float* be    = (const float*)d_in[5];
    const float* asrc  = (const float*)d_in[6];
    const float* atgt  = (const float*)d_in[7];
    const float* aedg  = (const float*)d_in[8];
    const float* Wsk   = (const float*)d_in[9];
    const float* gamma = (const float*)d_in[10];
    const float* beta  = (const float*)d_in[11];
    const float* bias  = (const float*)d_in[12];
    float* out = (float*)d_out;

    k1_proj<<<Nn / 8, 1024>>>(x, Wp, Wsk, asrc, atgt, We);
    k2_fused<<<128, 256>>>(e, conn, be, aedg, gamma, beta, bias, out);
}